// round 10
// baseline (speedup 1.0000x reference)
#include <cuda_runtime.h>
#include <math.h>

#define D 64
#define EPS_M 1e-7f
#define N_MAX 100001
#define NB 4            // nodes per warp-chunk (register-tiled GEMM)

__device__ float g_WT[D * D];       // g_WT[d*64 + c] = W[c][d]
__device__ int   g_off[N_MAX + 1];  // CSR offsets into sorted dst

// ---- single pre-kernel: CSR offsets + W transpose ----
__global__ void prep_kernel(const int* __restrict__ dst,
                            const float* __restrict__ W,
                            int n_nodes, int n_edges)
{
    const int i = blockIdx.x * blockDim.x + threadIdx.x;
    if (i < D * D) {
        int r = i >> 6, c = i & 63;       // W[r][c]
        g_WT[c * D + r] = W[i];
    }
    if (i <= n_nodes) {
        if (i == n_nodes) { g_off[i] = n_edges; }
        else {
            int lo = 0, hi = n_edges;
            while (lo < hi) { int mid = (lo + hi) >> 1; if (dst[mid] < i) lo = mid + 1; else hi = mid; }
            g_off[i] = lo;
        }
    }
}

// eps folded out: accumulate over r = relu(a+b); agg = sme/se + eps (exact)
__device__ __forceinline__ void edge_step4(const float4 a, const float4 b,
                                           float4& se, float4& sme)
{
    const float r0 = fmaxf(a.x + b.x, 0.f);
    const float r1 = fmaxf(a.y + b.y, 0.f);
    const float r2 = fmaxf(a.z + b.z, 0.f);
    const float r3 = fmaxf(a.w + b.w, 0.f);
    const float p0 = __expf(r0), p1 = __expf(r1);
    const float p2 = __expf(r2), p3 = __expf(r3);
    se.x += p0; se.y += p1; se.z += p2; se.w += p3;
    sme.x = fmaf(r0, p0, sme.x); sme.y = fmaf(r1, p1, sme.y);
    sme.z = fmaf(r2, p2, sme.z); sme.w = fmaf(r3, p3, sme.w);
}

__device__ __forceinline__ void red2(float4& v, int off) {
    v.x += __shfl_xor_sync(0xffffffffu, v.x, off);
    v.y += __shfl_xor_sync(0xffffffffu, v.y, off);
    v.z += __shfl_xor_sync(0xffffffffu, v.z, off);
    v.w += __shfl_xor_sync(0xffffffffu, v.w, off);
}

// ---- main kernel: warp handles NB consecutive nodes, then 4x64 mini-GEMM ----
__global__ void __launch_bounds__(256) genconv_kernel(
    const float* __restrict__ nf,     // [N, 64]
    const float* __restrict__ ef,     // [E, 64]
    const float* __restrict__ bvec,   // [64]
    const float* __restrict__ scale,  // [1]
    const int*   __restrict__ src,    // [E]
    float*       __restrict__ out,    // [N, 64]
    int n_nodes)
{
    __shared__ float sWT[D * D];          // 16 KB
    __shared__ float s_feat[8][NB][D];    // 8 KB

    const int lane = threadIdx.x & 31;
    const int wim  = threadIdx.x >> 5;
    const int oct  = lane >> 3;           // edge slot 0..3 (quarter-warp)
    const int ol   = lane & 7;            // lane within quarter
    const int c8   = ol * 8;              // channels c8..c8+7 in edge loop
    const int c2   = lane * 2;            // channels c2,c2+1 in GEMM
    const int gw   = (blockIdx.x * blockDim.x + threadIdx.x) >> 5;
    const int nwarps = (gridDim.x * blockDim.x) >> 5;

    {   // stage WT once per block
        const float4* s4 = (const float4*)g_WT;
        float4* d4 = (float4*)sWT;
        for (int i = threadIdx.x; i < (D * D) / 4; i += 256) d4[i] = s4[i];
    }
    __syncthreads();

    const float sc = scale[0];
    const float2 bv = *(const float2*)(bvec + c2);
    const int nchunks = (n_nodes + NB - 1) / NB;

    for (int chunk = gw; chunk < nchunks; chunk += nwarps) {
        const int base = chunk * NB;

        #pragma unroll
        for (int i = 0; i < NB; ++i) {
            const int node = base + i;
            float4 seA  = make_float4(0.f, 0.f, 0.f, 0.f);
            float4 seB  = make_float4(0.f, 0.f, 0.f, 0.f);
            float4 smeA = make_float4(0.f, 0.f, 0.f, 0.f);
            float4 smeB = make_float4(0.f, 0.f, 0.f, 0.f);
            float4 hA   = make_float4(0.f, 0.f, 0.f, 0.f);
            float4 hB   = make_float4(0.f, 0.f, 0.f, 0.f);

            if (node < n_nodes) {
                hA = *(const float4*)(nf + node * D + c8);
                hB = *(const float4*)(nf + node * D + c8 + 4);
                const int s    = g_off[node];
                const int eend = g_off[node + 1];
                // 4 edge slots (one per quarter-warp), no unroll:
                // full MLP engages at degree >= 4; ptxas prefetches 1 ahead.
                for (int e = s + oct; e < eend; e += 4) {
                    const int sp = __ldg(&src[e]);
                    const float4 b0 = __ldcs((const float4*)(ef + (size_t)e * D + c8));
                    const float4 b1 = __ldcs((const float4*)(ef + (size_t)e * D + c8 + 4));
                    const float4 a0 = *(const float4*)(nf + sp * D + c8);
                    const float4 a1 = *(const float4*)(nf + sp * D + c8 + 4);
                    edge_step4(a0, b0, seA, smeA);
                    edge_step4(a1, b1, seB, smeB);
                }
            }
            // combine the 4 edge slots (xor 8 and 16 across quarter-warps)
            red2(seA, 8);  red2(seA, 16);
            red2(seB, 8);  red2(seB, 16);
            red2(smeA, 8); red2(smeA, 16);
            red2(smeB, 8); red2(smeB, 16);

            float4 aggA, aggB;   // eps folded back in (exact)
            aggA.x = (seA.x > 0.f) ? (smeA.x / seA.x + EPS_M) : 0.f;
            aggA.y = (seA.y > 0.f) ? (smeA.y / seA.y + EPS_M) : 0.f;
            aggA.z = (seA.z > 0.f) ? (smeA.z / seA.z + EPS_M) : 0.f;
            aggA.w = (seA.w > 0.f) ? (smeA.w / seA.w + EPS_M) : 0.f;
            aggB.x = (seB.x > 0.f) ? (smeB.x / seB.x + EPS_M) : 0.f;
            aggB.y = (seB.y > 0.f) ? (smeB.y / seB.y + EPS_M) : 0.f;
            aggB.z = (seB.z > 0.f) ? (smeB.z / seB.z + EPS_M) : 0.f;
            aggB.w = (seB.w > 0.f) ? (smeB.w / seB.w + EPS_M) : 0.f;

            float a2s = fmaf(aggA.x, aggA.x, fmaf(aggA.y, aggA.y, fmaf(aggA.z, aggA.z, aggA.w * aggA.w)));
            a2s = fmaf(aggB.x, aggB.x, fmaf(aggB.y, aggB.y, fmaf(aggB.z, aggB.z, fmaf(aggB.w, aggB.w, a2s))));
            float h2s = fmaf(hA.x, hA.x, fmaf(hA.y, hA.y, fmaf(hA.z, hA.z, hA.w * hA.w)));
            h2s = fmaf(hB.x, hB.x, fmaf(hB.y, hB.y, fmaf(hB.z, hB.z, fmaf(hB.w, hB.w, h2s))));
            // sum across the 8 lanes of a quarter (all quarters identical now)
            #pragma unroll
            for (int o = 4; o > 0; o >>= 1) {
                a2s += __shfl_xor_sync(0xffffffffu, a2s, o);
                h2s += __shfl_xor_sync(0xffffffffu, h2s, o);
            }

            const float coef = (sqrtf(h2s) * sc) / fmaxf(sqrtf(a2s), 1e-12f);
            if (oct == 0) {      // lanes 0..7 store the 64-wide feature row
                float4 fA, fB;
                fA.x = fmaf(aggA.x, coef, hA.x);
                fA.y = fmaf(aggA.y, coef, hA.y);
                fA.z = fmaf(aggA.z, coef, hA.z);
                fA.w = fmaf(aggA.w, coef, hA.w);
                fB.x = fmaf(aggB.x, coef, hB.x);
                fB.y = fmaf(aggB.y, coef, hB.y);
                fB.z = fmaf(aggB.z, coef, hB.z);
                fB.w = fmaf(aggB.w, coef, hB.w);
                *(float4*)&s_feat[wim][i][c8]     = fA;
                *(float4*)&s_feat[wim][i][c8 + 4] = fB;
            }
        }
        __syncwarp();

        // mini-GEMM: out[base..base+3][c2,c2+1] = b + feat @ WT
        float2 acc[NB];
        #pragma unroll
        for (int i = 0; i < NB; ++i) acc[i] = bv;

        #pragma unroll
        for (int d4 = 0; d4 < D; d4 += 4) {
            const float2 w0 = *(const float2*)(sWT + (d4 + 0) * D + c2);
            const float2 w1 = *(const float2*)(sWT + (d4 + 1) * D + c2);
            const float2 w2 = *(const float2*)(sWT + (d4 + 2) * D + c2);
            const float2 w3 = *(const float2*)(sWT + (d4 + 3) * D + c2);
            #pragma unroll
            for (int i = 0; i < NB; ++i) {
                const float4 f = *(const float4*)&s_feat[wim][i][d4];  // broadcast
                acc[i].x = fmaf(f.x, w0.x, acc[i].x); acc[i].y = fmaf(f.x, w0.y, acc[i].y);
                acc[i].x = fmaf(f.y, w1.x, acc[i].x); acc[i].y = fmaf(f.y, w1.y, acc[i].y);
                acc[i].x = fmaf(f.z, w2.x, acc[i].x); acc[i].y = fmaf(f.z, w2.y, acc[i].y);
                acc[i].x = fmaf(f.w, w3.x, acc[i].x); acc[i].y = fmaf(f.w, w3.y, acc[i].y);
            }
        }
        #pragma unroll
        for (int i = 0; i < NB; ++i)
            if (base + i < n_nodes)
                *(float2*)(out + (size_t)(base + i) * D + c2) = acc[i];
        __syncwarp();   // protect s_feat WAR for next chunk
    }
}

extern "C" void kernel_launch(void* const* d_in, const int* in_sizes, int n_in,
                              void* d_out, int out_size)
{
    const float* nf    = (const float*)d_in[0];
    const float* ef    = (const float*)d_in[1];
    const float* W     = (const float*)d_in[2];
    const float* bvec  = (const float*)d_in[3];
    const float* scale = (const float*)d_in[4];
    const int*   src   = (const int*)d_in[5];
    const int*   dst   = (const int*)d_in[6];
    float* out = (float*)d_out;

    const int n_nodes = in_sizes[0] / D;
    const int n_edges = in_sizes[5];

    prep_kernel<<<(n_nodes + 256) / 256, 256>>>(dst, W, n_nodes, n_edges);
    genconv_kernel<<<1480, 256>>>(nf, ef, bvec, scale, src, out, n_nodes);
}